// round 10
// baseline (speedup 1.0000x reference)
#include <cuda_runtime.h>
#include <cstdint>

// ---------------------------------------------------------------------------
// GAT (3 layers, single head) on GB300 — CSR + smem-weight edition.
//  0: x [N, F_IN] f32
//  1: edge_index [2, E] (runtime-detected int32 vs int64)
//  2..5:  W1 [F_IN,64], a_src1[64], a_dst1[64], b1[64]
//  6..9:  W2, as2, ad2, b2     10..13: W3, as3, ad3, b3
// output: [N, 64] f32
// ---------------------------------------------------------------------------

#define HID 64
#define NMAX 131072
#define EMAX 3400000
#define SCAN_B 512
#define WCAP 128   // per-warp smem weight-cache slots

__device__ __align__(16) int      g_csrc[EMAX];     // CSR: src ids grouped by dst
__device__ __align__(16) int      g_cnt[NMAX];      // histogram, then fill cursor
__device__ __align__(16) int      g_off[NMAX + 1];  // CSR row offsets
__device__ __align__(16) int      g_bsum[1024];
__device__ __align__(16) float    g_H[(size_t)NMAX * HID];   // post-GEMM hidden
__device__ __align__(16) float    g_O[(size_t)NMAX * HID];   // aggregated output
__device__ __align__(16) float    g_es[NMAX];
__device__ __align__(16) float    g_ed[NMAX];
__device__ __align__(16) float    g_selfe[NMAX];
__device__ int g_is32;

__device__ __forceinline__ float leaky(float v) { return v > 0.f ? v : 0.2f * v; }

// ---------------------------------------------------------------------------
// dtype detection: int32 buffer read as u64 packs two ids -> values >= 2^32
// ---------------------------------------------------------------------------
__global__ void detect_dtype(const unsigned long long* __restrict__ ei, int nscan) {
    __shared__ int flag;
    if (threadIdx.x == 0) flag = 0;
    __syncthreads();
    for (int j = threadIdx.x; j < nscan; j += blockDim.x)
        if (ei[j] >= 0x100000000ull) flag = 1;
    __syncthreads();
    if (threadIdx.x == 0) g_is32 = flag;
}

__device__ __forceinline__ int load_id(const void* eiv, size_t idx) {
    if (g_is32) return ((const int*)eiv)[idx];
    return (int)((const long long*)eiv)[idx];
}

// ---------------------------------------------------------------------------
// CSR build (reads edge_index directly; no staging arrays)
// ---------------------------------------------------------------------------
__global__ void zero_cnt(int N) {
    int i = blockIdx.x * blockDim.x + threadIdx.x;
    if (i < N) g_cnt[i] = 0;
}
__global__ void hist_k(const void* __restrict__ eiv, int E, int N) {
    int i = blockIdx.x * blockDim.x + threadIdx.x;
    if (i >= E) return;
    int d = load_id(eiv, (size_t)E + i);
    d = min(max(d, 0), N - 1);
    atomicAdd(&g_cnt[d], 1);
}
// per-block inclusive scan of g_cnt chunks -> g_off[i+1]; block totals -> g_bsum
__global__ void __launch_bounds__(SCAN_B) scan_block(int N) {
    __shared__ int ws[SCAN_B / 32];
    int tid = threadIdx.x;
    int gi = blockIdx.x * SCAN_B + tid;
    int v = (gi < N) ? g_cnt[gi] : 0;
    int lane = tid & 31, wid = tid >> 5;
    int x = v;
#pragma unroll
    for (int o = 1; o < 32; o <<= 1) {
        int y = __shfl_up_sync(0xffffffffu, x, o);
        if (lane >= o) x += y;
    }
    if (lane == 31) ws[wid] = x;
    __syncthreads();
    if (wid == 0) {
        int t = (lane < SCAN_B / 32) ? ws[lane] : 0;
#pragma unroll
        for (int o = 1; o < SCAN_B / 32; o <<= 1) {
            int y = __shfl_up_sync(0xffffffffu, t, o);
            if (lane >= o) t += y;
        }
        if (lane < SCAN_B / 32) ws[lane] = t;
    }
    __syncthreads();
    int incl = x + (wid > 0 ? ws[wid - 1] : 0);
    if (gi < N) g_off[gi + 1] = incl;
    if (tid == SCAN_B - 1) g_bsum[blockIdx.x] = incl;
}
// exclusive scan of block sums (nb <= 512), single block
__global__ void __launch_bounds__(SCAN_B) scan_bsums(int nb) {
    __shared__ int ws[SCAN_B / 32];
    int tid = threadIdx.x;
    int v = (tid < nb) ? g_bsum[tid] : 0;
    int lane = tid & 31, wid = tid >> 5;
    int x = v;
#pragma unroll
    for (int o = 1; o < 32; o <<= 1) {
        int y = __shfl_up_sync(0xffffffffu, x, o);
        if (lane >= o) x += y;
    }
    if (lane == 31) ws[wid] = x;
    __syncthreads();
    if (wid == 0) {
        int t = (lane < SCAN_B / 32) ? ws[lane] : 0;
#pragma unroll
        for (int o = 1; o < SCAN_B / 32; o <<= 1) {
            int y = __shfl_up_sync(0xffffffffu, t, o);
            if (lane >= o) t += y;
        }
        if (lane < SCAN_B / 32) ws[lane] = t;
    }
    __syncthreads();
    int incl = x + (wid > 0 ? ws[wid - 1] : 0);
    if (tid < nb) g_bsum[tid] = incl - v;   // exclusive
}
__global__ void add_offsets(int N) {
    int gi = blockIdx.x * blockDim.x + threadIdx.x;
    if (gi == 0) g_off[0] = 0;
    if (gi < N) g_off[gi + 1] += g_bsum[gi / SCAN_B];
}
__global__ void copy_cursor(int N) {
    int i = blockIdx.x * blockDim.x + threadIdx.x;
    if (i < N) g_cnt[i] = g_off[i];
}
__global__ void fill_csr(const void* __restrict__ eiv, int E, int N) {
    int i = blockIdx.x * blockDim.x + threadIdx.x;
    if (i >= E) return;
    int s = load_id(eiv, i);
    int d = load_id(eiv, (size_t)E + i);
    s = min(max(s, 0), N - 1);
    d = min(max(d, 0), N - 1);
    int pos = atomicAdd(&g_cnt[d], 1);
    g_csrc[pos] = s;
}

// ---------------------------------------------------------------------------
// GEMM: g_H[M,64] = act(X[M,K]) @ W[K,64] with fused es/ed/selfe epilogue
// ---------------------------------------------------------------------------
template<bool RELU, bool FROM_GO>
__global__ void __launch_bounds__(256)
gemm_k(const float* __restrict__ X, const float* __restrict__ W,
       const float* __restrict__ as, const float* __restrict__ ad,
       int M, int K) {
    __shared__ float Ws[64 * 64];
    __shared__ float Xs[64 * 68];

    const int tid = threadIdx.x;
    const int tx = tid & 15;
    const int ty = tid >> 4;
    const int row0 = blockIdx.x << 6;

    const float* __restrict__ Xp = FROM_GO ? g_O : X;

    float acc[4][4];
#pragma unroll
    for (int r = 0; r < 4; r++)
#pragma unroll
        for (int c = 0; c < 4; c++) acc[r][c] = 0.f;

    for (int kk = 0; kk < K; kk += 64) {
#pragma unroll
        for (int p = 0; p < 4; p++) {
            int r = ty + (p << 4);
            int c = tx << 2;
            *(float4*)&Ws[r * 64 + c] = *(const float4*)&W[(size_t)(kk + r) * HID + c];
            int grow = row0 + r;
            float4 v = make_float4(0.f, 0.f, 0.f, 0.f);
            if (grow < M) {
                v = *(const float4*)&Xp[(size_t)grow * K + kk + c];
                if (RELU) {
                    v.x = fmaxf(v.x, 0.f); v.y = fmaxf(v.y, 0.f);
                    v.z = fmaxf(v.z, 0.f); v.w = fmaxf(v.w, 0.f);
                }
            }
            *(float4*)&Xs[r * 68 + c] = v;
        }
        __syncthreads();

#pragma unroll
        for (int k = 0; k < 64; k++) {
            float4 b4 = *(float4*)&Ws[k * 64 + (tx << 2)];
            float a0 = Xs[(ty * 4 + 0) * 68 + k];
            float a1 = Xs[(ty * 4 + 1) * 68 + k];
            float a2 = Xs[(ty * 4 + 2) * 68 + k];
            float a3 = Xs[(ty * 4 + 3) * 68 + k];
            acc[0][0] += a0 * b4.x; acc[0][1] += a0 * b4.y; acc[0][2] += a0 * b4.z; acc[0][3] += a0 * b4.w;
            acc[1][0] += a1 * b4.x; acc[1][1] += a1 * b4.y; acc[1][2] += a1 * b4.z; acc[1][3] += a1 * b4.w;
            acc[2][0] += a2 * b4.x; acc[2][1] += a2 * b4.y; acc[2][2] += a2 * b4.z; acc[2][3] += a2 * b4.w;
            acc[3][0] += a3 * b4.x; acc[3][1] += a3 * b4.y; acc[3][2] += a3 * b4.z; acc[3][3] += a3 * b4.w;
        }
        __syncthreads();
    }

#pragma unroll
    for (int r = 0; r < 4; r++) {
        int grow = row0 + ty * 4 + r;
        if (grow < M) {
            *(float4*)&g_H[(size_t)grow * HID + (tx << 2)] =
                make_float4(acc[r][0], acc[r][1], acc[r][2], acc[r][3]);
        }
    }

    float4 as4 = *(const float4*)&as[tx << 2];
    float4 ad4 = *(const float4*)&ad[tx << 2];
    float pes[4], ped[4];
#pragma unroll
    for (int r = 0; r < 4; r++) {
        pes[r] = acc[r][0] * as4.x + acc[r][1] * as4.y + acc[r][2] * as4.z + acc[r][3] * as4.w;
        ped[r] = acc[r][0] * ad4.x + acc[r][1] * ad4.y + acc[r][2] * ad4.z + acc[r][3] * ad4.w;
    }
#pragma unroll
    for (int o = 8; o; o >>= 1) {
#pragma unroll
        for (int r = 0; r < 4; r++) {
            pes[r] += __shfl_xor_sync(0xffffffffu, pes[r], o);
            ped[r] += __shfl_xor_sync(0xffffffffu, ped[r], o);
        }
    }
    if (tx == 0) {
#pragma unroll
        for (int r = 0; r < 4; r++) {
            int grow = row0 + ty * 4 + r;
            if (grow < M) {
                float es = pes[r], ed = ped[r];
                g_es[grow] = es;
                g_ed[grow] = ed;
                g_selfe[grow] = leaky(es + ed);
            }
        }
    }
}

// ---------------------------------------------------------------------------
// Fused softmax + aggregate: one warp per dst node, zero atomics, zero
// global edge-weight traffic (per-warp smem cache; rare deg>WCAP edges
// recompute their weight inline).
// ---------------------------------------------------------------------------
template<bool FINAL>
__global__ void __launch_bounds__(256)
agg_k(const float* __restrict__ b, float* __restrict__ out, int N) {
    __shared__ float ew[8][WCAP];
    int wid = threadIdx.x >> 5;
    int lane = threadIdx.x & 31;
    int node = (blockIdx.x << 3) + wid;
    if (node >= N) return;

    int beg = g_off[node];
    int deg = g_off[node + 1] - beg;
    float edn = g_ed[node];
    float selfe = g_selfe[node];

    // pass A: logits -> smem cache, register max
    float m = selfe;
    for (int j = lane; j < deg; j += 32) {
        int s = g_csrc[beg + j];
        float e = leaky(g_es[s] + edn);
        if (j < WCAP) ew[wid][j] = e;
        m = fmaxf(m, e);
    }
#pragma unroll
    for (int o = 16; o; o >>= 1) m = fmaxf(m, __shfl_xor_sync(0xffffffffu, m, o));

    // pass B: exp in-place + sum
    float wself = __expf(selfe - m);
    float ssum = (lane == 0) ? wself : 0.f;
    int cached = min(deg, WCAP);
    for (int j = lane; j < cached; j += 32) {
        float ex = __expf(ew[wid][j] - m);
        ew[wid][j] = ex;
        ssum += ex;
    }
    for (int j = WCAP + lane; j < deg; j += 32) {   // rare overflow
        int s = g_csrc[beg + j];
        ssum += __expf(leaky(g_es[s] + edn) - m);
    }
#pragma unroll
    for (int o = 16; o; o >>= 1) ssum += __shfl_xor_sync(0xffffffffu, ssum, o);
    __syncwarp();

    // pass C: weighted feature gather, 2 edges/iter (16 lanes x float4 each)
    int half = lane >> 4;
    int q = (lane & 15) << 2;
    float4 acc = make_float4(0.f, 0.f, 0.f, 0.f);
    if (half == 0) {
        float4 hv = *(const float4*)&g_H[(size_t)node * HID + q];
        acc.x = wself * hv.x; acc.y = wself * hv.y;
        acc.z = wself * hv.z; acc.w = wself * hv.w;
    }
    for (int j = half; j < deg; j += 2) {
        int s = g_csrc[beg + j];
        float wt = (j < WCAP) ? ew[wid][j]
                              : __expf(leaky(g_es[s] + edn) - m);  // rare
        float4 v = *(const float4*)&g_H[(size_t)s * HID + q];
        acc.x += wt * v.x; acc.y += wt * v.y;
        acc.z += wt * v.z; acc.w += wt * v.w;
    }
    acc.x += __shfl_xor_sync(0xffffffffu, acc.x, 16);
    acc.y += __shfl_xor_sync(0xffffffffu, acc.y, 16);
    acc.z += __shfl_xor_sync(0xffffffffu, acc.z, 16);
    acc.w += __shfl_xor_sync(0xffffffffu, acc.w, 16);

    if (half == 0) {
        float inv = 1.f / ssum;
        float4 b4 = *(const float4*)&b[q];
        float* dst = FINAL ? out : g_O;
        *(float4*)&dst[(size_t)node * HID + q] =
            make_float4(acc.x * inv + b4.x, acc.y * inv + b4.y,
                        acc.z * inv + b4.z, acc.w * inv + b4.w);
    }
}

// ---------------------------------------------------------------------------
// host driver
// ---------------------------------------------------------------------------
extern "C" void kernel_launch(void* const* d_in, const int* in_sizes, int n_in,
                              void* d_out, int out_size) {
    const float* x   = (const float*)d_in[0];
    const void*  ei  = d_in[1];
    const float* W1  = (const float*)d_in[2];
    const float* as1 = (const float*)d_in[3];
    const float* ad1 = (const float*)d_in[4];
    const float* b1  = (const float*)d_in[5];
    const float* W2  = (const float*)d_in[6];
    const float* as2 = (const float*)d_in[7];
    const float* ad2 = (const float*)d_in[8];
    const float* b2  = (const float*)d_in[9];
    const float* W3  = (const float*)d_in[10];
    const float* as3 = (const float*)d_in[11];
    const float* ad3 = (const float*)d_in[12];
    const float* b3  = (const float*)d_in[13];

    int hid = in_sizes[3];            // 64
    int fin = in_sizes[2] / hid;      // 128
    int N   = in_sizes[0] / fin;
    int E   = in_sizes[1] / 2;
    float* out = (float*)d_out;

    // edge index dtype detect
    int nscan = 4096;
    if (nscan > E / 2) nscan = E / 2 > 0 ? E / 2 : 1;
    detect_dtype<<<1, 256>>>((const unsigned long long*)ei, nscan);

    // CSR build (once, reused by 3 layers) — reads edge_index directly
    int nb = (N + SCAN_B - 1) / SCAN_B;
    zero_cnt<<<(N + 255) / 256, 256>>>(N);
    hist_k<<<(E + 255) / 256, 256>>>(ei, E, N);
    scan_block<<<nb, SCAN_B>>>(N);
    scan_bsums<<<1, SCAN_B>>>(nb);
    add_offsets<<<(N + 255) / 256, 256>>>(N);
    copy_cursor<<<(N + 255) / 256, 256>>>(N);
    fill_csr<<<(E + 255) / 256, 256>>>(ei, E, N);

    int gblk = (N + 63) / 64;
    int ablk = (N + 7) / 8;   // 8 warps (nodes) per 256-thread block

    // layer 1
    gemm_k<false, false><<<gblk, 256>>>(x, W1, as1, ad1, N, fin);
    agg_k<false><<<ablk, 256>>>(b1, nullptr, N);
    // layer 2
    gemm_k<true, true><<<gblk, 256>>>(nullptr, W2, as2, ad2, N, hid);
    agg_k<false><<<ablk, 256>>>(b2, nullptr, N);
    // layer 3
    gemm_k<true, true><<<gblk, 256>>>(nullptr, W3, as3, ad3, N, hid);
    agg_k<true><<<ablk, 256>>>(b3, out, N);
}

// round 11
// speedup vs baseline: 1.0755x; 1.0755x over previous
#include <cuda_runtime.h>
#include <cstdint>

// ---------------------------------------------------------------------------
// GAT (3 layers, single head) on GB300 — CSR + 128x64 GEMM edition.
//  0: x [N, F_IN] f32
//  1: edge_index [2, E] (runtime-detected int32 vs int64)
//  2..5:  W1 [F_IN,64], a_src1[64], a_dst1[64], b1[64]
//  6..9:  W2, as2, ad2, b2     10..13: W3, as3, ad3, b3
// output: [N, 64] f32
// ---------------------------------------------------------------------------

#define HID 64
#define NMAX 131072
#define EMAX 3400000
#define SCAN_B 512

__device__ __align__(16) int      g_src[EMAX];
__device__ __align__(16) int      g_dst[EMAX];
__device__ __align__(16) int      g_csrc[EMAX];     // CSR: src ids grouped by dst
__device__ __align__(16) float    g_ew[EMAX];       // per-CSR-slot e, then exp(e-m)
__device__ __align__(16) int      g_cnt[NMAX];      // histogram, then fill cursor
__device__ __align__(16) int      g_off[NMAX + 1];  // CSR row offsets
__device__ __align__(16) int      g_bsum[1024];
__device__ __align__(16) float    g_H[(size_t)NMAX * HID];   // post-GEMM hidden
__device__ __align__(16) float    g_O[(size_t)NMAX * HID];   // aggregated output
__device__ __align__(16) float    g_es[NMAX];
__device__ __align__(16) float    g_ed[NMAX];
__device__ __align__(16) float    g_selfe[NMAX];
__device__ int g_is32;

__device__ __forceinline__ float leaky(float v) { return v > 0.f ? v : 0.2f * v; }

// ---------------------------------------------------------------------------
// dtype detection: int32 buffer read as u64 packs two ids -> values >= 2^32
// ---------------------------------------------------------------------------
__global__ void detect_dtype(const unsigned long long* __restrict__ ei, int nscan) {
    __shared__ int flag;
    if (threadIdx.x == 0) flag = 0;
    __syncthreads();
    for (int j = threadIdx.x; j < nscan; j += blockDim.x)
        if (ei[j] >= 0x100000000ull) flag = 1;
    __syncthreads();
    if (threadIdx.x == 0) g_is32 = flag;
}

__global__ void conv_idx(const void* __restrict__ eiv, int E, int N) {
    int i = blockIdx.x * blockDim.x + threadIdx.x;
    if (i >= E) return;
    int s, d;
    if (g_is32) {
        const int* p = (const int*)eiv;
        s = p[i]; d = p[(size_t)E + i];
    } else {
        const long long* p = (const long long*)eiv;
        s = (int)p[i]; d = (int)p[(size_t)E + i];
    }
    s = min(max(s, 0), N - 1);
    d = min(max(d, 0), N - 1);
    g_src[i] = s;
    g_dst[i] = d;
}

// ---------------------------------------------------------------------------
// CSR build
// ---------------------------------------------------------------------------
__global__ void zero_cnt(int N) {
    int i = blockIdx.x * blockDim.x + threadIdx.x;
    if (i < N) g_cnt[i] = 0;
}
__global__ void hist_k(int E) {
    int i = blockIdx.x * blockDim.x + threadIdx.x;
    if (i < E) atomicAdd(&g_cnt[g_dst[i]], 1);
}
__global__ void __launch_bounds__(SCAN_B) scan_block(int N) {
    __shared__ int ws[SCAN_B / 32];
    int tid = threadIdx.x;
    int gi = blockIdx.x * SCAN_B + tid;
    int v = (gi < N) ? g_cnt[gi] : 0;
    int lane = tid & 31, wid = tid >> 5;
    int x = v;
#pragma unroll
    for (int o = 1; o < 32; o <<= 1) {
        int y = __shfl_up_sync(0xffffffffu, x, o);
        if (lane >= o) x += y;
    }
    if (lane == 31) ws[wid] = x;
    __syncthreads();
    if (wid == 0) {
        int t = (lane < SCAN_B / 32) ? ws[lane] : 0;
#pragma unroll
        for (int o = 1; o < SCAN_B / 32; o <<= 1) {
            int y = __shfl_up_sync(0xffffffffu, t, o);
            if (lane >= o) t += y;
        }
        if (lane < SCAN_B / 32) ws[lane] = t;
    }
    __syncthreads();
    int incl = x + (wid > 0 ? ws[wid - 1] : 0);
    if (gi < N) g_off[gi + 1] = incl;
    if (tid == SCAN_B - 1) g_bsum[blockIdx.x] = incl;
}
__global__ void __launch_bounds__(SCAN_B) scan_bsums(int nb) {
    __shared__ int ws[SCAN_B / 32];
    int tid = threadIdx.x;
    int v = (tid < nb) ? g_bsum[tid] : 0;
    int lane = tid & 31, wid = tid >> 5;
    int x = v;
#pragma unroll
    for (int o = 1; o < 32; o <<= 1) {
        int y = __shfl_up_sync(0xffffffffu, x, o);
        if (lane >= o) x += y;
    }
    if (lane == 31) ws[wid] = x;
    __syncthreads();
    if (wid == 0) {
        int t = (lane < SCAN_B / 32) ? ws[lane] : 0;
#pragma unroll
        for (int o = 1; o < SCAN_B / 32; o <<= 1) {
            int y = __shfl_up_sync(0xffffffffu, t, o);
            if (lane >= o) t += y;
        }
        if (lane < SCAN_B / 32) ws[lane] = t;
    }
    __syncthreads();
    int incl = x + (wid > 0 ? ws[wid - 1] : 0);
    if (tid < nb) g_bsum[tid] = incl - v;   // exclusive
}
__global__ void add_offsets(int N) {
    int gi = blockIdx.x * blockDim.x + threadIdx.x;
    if (gi == 0) g_off[0] = 0;
    if (gi < N) g_off[gi + 1] += g_bsum[gi / SCAN_B];
}
__global__ void copy_cursor(int N) {
    int i = blockIdx.x * blockDim.x + threadIdx.x;
    if (i < N) g_cnt[i] = g_off[i];
}
__global__ void fill_csr(int E) {
    int i = blockIdx.x * blockDim.x + threadIdx.x;
    if (i >= E) return;
    int d = g_dst[i];
    int pos = atomicAdd(&g_cnt[d], 1);
    g_csrc[pos] = g_src[i];
}

// ---------------------------------------------------------------------------
// GEMM: g_H[M,64] = act(X[M,K]) @ W[K,64], 128x64 tile, 256 thr, 8x4/thread.
// K chunked by 32. Xs stored scalar w/ stride 33 (8*33 % 32 == 8: the two
// ty-groups in a warp hit different banks -> conflict-free broadcasts).
// Fused epilogue: es/ed/selfe from accumulators.
// ---------------------------------------------------------------------------
#define KC 32
template<bool RELU, bool FROM_GO>
__global__ void __launch_bounds__(256)
gemm_k(const float* __restrict__ X, const float* __restrict__ W,
       const float* __restrict__ as, const float* __restrict__ ad,
       int M, int K) {
    __shared__ float Ws[KC * 64];        // 8 KB
    __shared__ float Xs[128 * 33];       // 16.5 KB

    const int tid = threadIdx.x;
    const int tx = tid & 15;             // col group (4 cols)
    const int ty = tid >> 4;             // row group (8 rows)
    const int row0 = blockIdx.x << 7;

    const float* __restrict__ Xp = FROM_GO ? g_O : X;

    float acc[8][4];
#pragma unroll
    for (int r = 0; r < 8; r++)
#pragma unroll
        for (int c = 0; c < 4; c++) acc[r][c] = 0.f;

    for (int kk = 0; kk < K; kk += KC) {
        // load Ws chunk [KC,64]: 512 float4, 2 per thread
#pragma unroll
        for (int p = 0; p < 2; p++) {
            int j = tid + (p << 8);          // 0..511
            int r = j >> 4;                  // 0..31
            int cp = (j & 15) << 2;
            *(float4*)&Ws[r * 64 + cp] = *(const float4*)&W[(size_t)(kk + r) * HID + cp];
        }
        // load Xs chunk [128,KC]: 1024 float4, 4 per thread; store scalar
#pragma unroll
        for (int p = 0; p < 4; p++) {
            int j = tid + (p << 8);          // 0..1023
            int r = j >> 3;                  // 0..127
            int cp = (j & 7) << 2;           // 0..28
            int grow = row0 + r;
            float4 v = make_float4(0.f, 0.f, 0.f, 0.f);
            if (grow < M) {
                v = *(const float4*)&Xp[(size_t)grow * K + kk + cp];
                if (RELU) {
                    v.x = fmaxf(v.x, 0.f); v.y = fmaxf(v.y, 0.f);
                    v.z = fmaxf(v.z, 0.f); v.w = fmaxf(v.w, 0.f);
                }
            }
            float* xs = &Xs[r * 33 + cp];
            xs[0] = v.x; xs[1] = v.y; xs[2] = v.z; xs[3] = v.w;
        }
        __syncthreads();

#pragma unroll
        for (int k = 0; k < KC; k++) {
            float4 b4 = *(float4*)&Ws[k * 64 + (tx << 2)];
            float a[8];
#pragma unroll
            for (int r = 0; r < 8; r++) a[r] = Xs[(ty * 8 + r) * 33 + k];
#pragma unroll
            for (int r = 0; r < 8; r++) {
                acc[r][0] += a[r] * b4.x;
                acc[r][1] += a[r] * b4.y;
                acc[r][2] += a[r] * b4.z;
                acc[r][3] += a[r] * b4.w;
            }
        }
        __syncthreads();
    }

    // store H tile
#pragma unroll
    for (int r = 0; r < 8; r++) {
        int grow = row0 + ty * 8 + r;
        if (grow < M) {
            *(float4*)&g_H[(size_t)grow * HID + (tx << 2)] =
                make_float4(acc[r][0], acc[r][1], acc[r][2], acc[r][3]);
        }
    }

    // fused attention-logit epilogue (reduce across the 16 tx lanes)
    float4 as4 = *(const float4*)&as[tx << 2];
    float4 ad4 = *(const float4*)&ad[tx << 2];
    float pes[8], ped[8];
#pragma unroll
    for (int r = 0; r < 8; r++) {
        pes[r] = acc[r][0] * as4.x + acc[r][1] * as4.y + acc[r][2] * as4.z + acc[r][3] * as4.w;
        ped[r] = acc[r][0] * ad4.x + acc[r][1] * ad4.y + acc[r][2] * ad4.z + acc[r][3] * ad4.w;
    }
#pragma unroll
    for (int o = 8; o; o >>= 1) {
#pragma unroll
        for (int r = 0; r < 8; r++) {
            pes[r] += __shfl_xor_sync(0xffffffffu, pes[r], o);
            ped[r] += __shfl_xor_sync(0xffffffffu, ped[r], o);
        }
    }
    if (tx == 0) {
#pragma unroll
        for (int r = 0; r < 8; r++) {
            int grow = row0 + ty * 8 + r;
            if (grow < M) {
                float es = pes[r], ed = ped[r];
                g_es[grow] = es;
                g_ed[grow] = ed;
                g_selfe[grow] = leaky(es + ed);
            }
        }
    }
}

// ---------------------------------------------------------------------------
// Fused softmax + aggregate: one warp per dst node, zero atomics. (R9 form)
// ---------------------------------------------------------------------------
template<bool FINAL>
__global__ void __launch_bounds__(256)
agg_k(const float* __restrict__ b, float* __restrict__ out, int N) {
    int node = (blockIdx.x * 256 + threadIdx.x) >> 5;
    int lane = threadIdx.x & 31;
    if (node >= N) return;

    int beg = g_off[node], end = g_off[node + 1];
    float edn = g_ed[node];
    float selfe = g_selfe[node];

    // pass A: logits + max
    float m = selfe;
    for (int i = beg + lane; i < end; i += 32) {
        int s = g_csrc[i];
        float e = leaky(g_es[s] + edn);
        g_ew[i] = e;
        m = fmaxf(m, e);
    }
#pragma unroll
    for (int o = 16; o; o >>= 1) m = fmaxf(m, __shfl_xor_sync(0xffffffffu, m, o));

    // pass B: exp + sum
    float wself = __expf(selfe - m);
    float ssum = (lane == 0) ? wself : 0.f;
    for (int i = beg + lane; i < end; i += 32) {
        float ex = __expf(g_ew[i] - m);
        g_ew[i] = ex;
        ssum += ex;
    }
#pragma unroll
    for (int o = 16; o; o >>= 1) ssum += __shfl_xor_sync(0xffffffffu, ssum, o);

    // pass C: weighted feature gather, 2 edges/iter (16 lanes x float4 each)
    int half = lane >> 4;
    int q = (lane & 15) << 2;
    float4 acc = make_float4(0.f, 0.f, 0.f, 0.f);
    if (half == 0) {
        float4 hv = *(const float4*)&g_H[(size_t)node * HID + q];
        acc.x = wself * hv.x; acc.y = wself * hv.y;
        acc.z = wself * hv.z; acc.w = wself * hv.w;
    }
    for (int i = beg + half; i < end; i += 2) {
        int s = g_csrc[i];
        float wt = g_ew[i];
        float4 v = *(const float4*)&g_H[(size_t)s * HID + q];
        acc.x += wt * v.x; acc.y += wt * v.y;
        acc.z += wt * v.z; acc.w += wt * v.w;
    }
    acc.x += __shfl_xor_sync(0xffffffffu, acc.x, 16);
    acc.y += __shfl_xor_sync(0xffffffffu, acc.y, 16);
    acc.z += __shfl_xor_sync(0xffffffffu, acc.z, 16);
    acc.w += __shfl_xor_sync(0xffffffffu, acc.w, 16);

    if (half == 0) {
        float inv = 1.f / ssum;
        float4 b4 = *(const float4*)&b[q];
        float* dst = FINAL ? out : g_O;
        *(float4*)&dst[(size_t)node * HID + q] =
            make_float4(acc.x * inv + b4.x, acc.y * inv + b4.y,
                        acc.z * inv + b4.z, acc.w * inv + b4.w);
    }
}

// ---------------------------------------------------------------------------
// host driver
// ---------------------------------------------------------------------------
extern "C" void kernel_launch(void* const* d_in, const int* in_sizes, int n_in,
                              void* d_out, int out_size) {
    const float* x   = (const float*)d_in[0];
    const void*  ei  = d_in[1];
    const float* W1  = (const float*)d_in[2];
    const float* as1 = (const float*)d_in[3];
    const float* ad1 = (const float*)d_in[4];
    const float* b1  = (const float*)d_in[5];
    const float* W2  = (const float*)d_in[6];
    const float* as2 = (const float*)d_in[7];
    const float* ad2 = (const float*)d_in[8];
    const float* b2  = (const float*)d_in[9];
    const float* W3  = (const float*)d_in[10];
    const float* as3 = (const float*)d_in[11];
    const float* ad3 = (const float*)d_in[12];
    const float* b3  = (const float*)d_in[13];

    int hid = in_sizes[3];            // 64
    int fin = in_sizes[2] / hid;      // 128
    int N   = in_sizes[0] / fin;
    int E   = in_sizes[1] / 2;
    float* out = (float*)d_out;

    // edge index dtype detect + convert
    int nscan = 4096;
    if (nscan > E / 2) nscan = E / 2 > 0 ? E / 2 : 1;
    detect_dtype<<<1, 256>>>((const unsigned long long*)ei, nscan);
    conv_idx<<<(E + 255) / 256, 256>>>(ei, E, N);

    // CSR build (once, reused by 3 layers)
    int nb = (N + SCAN_B - 1) / SCAN_B;
    zero_cnt<<<(N + 255) / 256, 256>>>(N);
    hist_k<<<(E + 255) / 256, 256>>>(E);
    scan_block<<<nb, SCAN_B>>>(N);
    scan_bsums<<<1, SCAN_B>>>(nb);
    add_offsets<<<(N + 255) / 256, 256>>>(N);
    copy_cursor<<<(N + 255) / 256, 256>>>(N);
    fill_csr<<<(E + 255) / 256, 256>>>(E);

    int gblk = (N + 127) / 128;
    int ablk = (N * 32 + 255) / 256;

    // layer 1
    gemm_k<false, false><<<gblk, 256>>>(x, W1, as1, ad1, N, fin);
    agg_k<false><<<ablk, 256>>>(b1, nullptr, N);
    // layer 2
    gemm_k<true, true><<<gblk, 256>>>(nullptr, W2, as2, ad2, N, hid);
    agg_k<false><<<ablk, 256>>>(b2, nullptr, N);
    // layer 3
    gemm_k<true, true><<<gblk, 256>>>(nullptr, W3, as3, ad3, N, hid);
    agg_k<true><<<ablk, 256>>>(b3, out, N);
}

// round 12
// speedup vs baseline: 1.1625x; 1.0809x over previous
#include <cuda_runtime.h>
#include <cuda_fp16.h>
#include <cstdint>

// ---------------------------------------------------------------------------
// GAT (3 layers, single head) on GB300 — CSR + fp16-gather edition.
//  0: x [N, F_IN] f32
//  1: edge_index [2, E] (runtime-detected int32 vs int64)
//  2..5:  W1 [F_IN,64], a_src1[64], a_dst1[64], b1[64]
//  6..9:  W2, as2, ad2, b2     10..13: W3, as3, ad3, b3
// output: [N, 64] f32
// ---------------------------------------------------------------------------

#define HID 64
#define NMAX 131072
#define EMAX 3400000
#define SCAN_B 512

__device__ __align__(16) int      g_csrc[EMAX];     // CSR: src ids grouped by dst
__device__ __align__(16) float    g_ew[EMAX];       // per-CSR-slot e, then exp(e-m)
__device__ __align__(16) int      g_cnt[NMAX];      // histogram, then fill cursor
__device__ __align__(16) int      g_off[NMAX + 1];  // CSR row offsets
__device__ __align__(16) int      g_bsum[1024];
__device__ __align__(16) __half   g_Hh[(size_t)NMAX * HID];  // hidden, fp16 (gather)
__device__ __align__(16) float    g_O[(size_t)NMAX * HID];   // aggregated output
__device__ __align__(16) float    g_es[NMAX];
__device__ __align__(16) float    g_ed[NMAX];
__device__ __align__(16) float    g_selfe[NMAX];
__device__ int g_is32;

__device__ __forceinline__ float leaky(float v) { return v > 0.f ? v : 0.2f * v; }

// ---------------------------------------------------------------------------
// dtype detection: int32 buffer read as u64 packs two ids -> values >= 2^32
// ---------------------------------------------------------------------------
__global__ void detect_dtype(const unsigned long long* __restrict__ ei, int nscan) {
    __shared__ int flag;
    if (threadIdx.x == 0) flag = 0;
    __syncthreads();
    for (int j = threadIdx.x; j < nscan; j += blockDim.x)
        if (ei[j] >= 0x100000000ull) flag = 1;
    __syncthreads();
    if (threadIdx.x == 0) g_is32 = flag;
}

__device__ __forceinline__ int load_id(const void* eiv, size_t idx) {
    if (g_is32) return ((const int*)eiv)[idx];
    return (int)((const long long*)eiv)[idx];
}

// ---------------------------------------------------------------------------
// CSR build (edge_index read directly; no staging arrays)
// ---------------------------------------------------------------------------
__global__ void zero_cnt(int N) {
    int i = blockIdx.x * blockDim.x + threadIdx.x;
    if (i < N) g_cnt[i] = 0;
}
__global__ void hist_k(const void* __restrict__ eiv, int E, int N) {
    int i = blockIdx.x * blockDim.x + threadIdx.x;
    if (i >= E) return;
    int d = load_id(eiv, (size_t)E + i);
    d = min(max(d, 0), N - 1);
    atomicAdd(&g_cnt[d], 1);
}
__global__ void __launch_bounds__(SCAN_B) scan_block(int N) {
    __shared__ int ws[SCAN_B / 32];
    int tid = threadIdx.x;
    int gi = blockIdx.x * SCAN_B + tid;
    int v = (gi < N) ? g_cnt[gi] : 0;
    int lane = tid & 31, wid = tid >> 5;
    int x = v;
#pragma unroll
    for (int o = 1; o < 32; o <<= 1) {
        int y = __shfl_up_sync(0xffffffffu, x, o);
        if (lane >= o) x += y;
    }
    if (lane == 31) ws[wid] = x;
    __syncthreads();
    if (wid == 0) {
        int t = (lane < SCAN_B / 32) ? ws[lane] : 0;
#pragma unroll
        for (int o = 1; o < SCAN_B / 32; o <<= 1) {
            int y = __shfl_up_sync(0xffffffffu, t, o);
            if (lane >= o) t += y;
        }
        if (lane < SCAN_B / 32) ws[lane] = t;
    }
    __syncthreads();
    int incl = x + (wid > 0 ? ws[wid - 1] : 0);
    if (gi < N) g_off[gi + 1] = incl;
    if (tid == SCAN_B - 1) g_bsum[blockIdx.x] = incl;
}
__global__ void __launch_bounds__(SCAN_B) scan_bsums(int nb) {
    __shared__ int ws[SCAN_B / 32];
    int tid = threadIdx.x;
    int v = (tid < nb) ? g_bsum[tid] : 0;
    int lane = tid & 31, wid = tid >> 5;
    int x = v;
#pragma unroll
    for (int o = 1; o < 32; o <<= 1) {
        int y = __shfl_up_sync(0xffffffffu, x, o);
        if (lane >= o) x += y;
    }
    if (lane == 31) ws[wid] = x;
    __syncthreads();
    if (wid == 0) {
        int t = (lane < SCAN_B / 32) ? ws[lane] : 0;
#pragma unroll
        for (int o = 1; o < SCAN_B / 32; o <<= 1) {
            int y = __shfl_up_sync(0xffffffffu, t, o);
            if (lane >= o) t += y;
        }
        if (lane < SCAN_B / 32) ws[lane] = t;
    }
    __syncthreads();
    int incl = x + (wid > 0 ? ws[wid - 1] : 0);
    if (tid < nb) g_bsum[tid] = incl - v;   // exclusive
}
__global__ void add_offsets(int N) {
    int gi = blockIdx.x * blockDim.x + threadIdx.x;
    if (gi == 0) g_off[0] = 0;
    if (gi < N) g_off[gi + 1] += g_bsum[gi / SCAN_B];
}
__global__ void copy_cursor(int N) {
    int i = blockIdx.x * blockDim.x + threadIdx.x;
    if (i < N) g_cnt[i] = g_off[i];
}
__global__ void fill_csr(const void* __restrict__ eiv, int E, int N) {
    int i = blockIdx.x * blockDim.x + threadIdx.x;
    if (i >= E) return;
    int s = load_id(eiv, i);
    int d = load_id(eiv, (size_t)E + i);
    s = min(max(s, 0), N - 1);
    d = min(max(d, 0), N - 1);
    int pos = atomicAdd(&g_cnt[d], 1);
    g_csrc[pos] = s;
}

// ---------------------------------------------------------------------------
// GEMM: act(X[M,K]) @ W[K,64] -> g_Hh (fp16), 128x64 tile, 8x4/thread.
// Fused epilogue: es/ed/selfe straight from fp32 accumulators.
// ---------------------------------------------------------------------------
#define KC 32
template<bool RELU, bool FROM_GO>
__global__ void __launch_bounds__(256)
gemm_k(const float* __restrict__ X, const float* __restrict__ W,
       const float* __restrict__ as, const float* __restrict__ ad,
       int M, int K) {
    __shared__ float Ws[KC * 64];        // 8 KB
    __shared__ float Xs[128 * 33];       // 16.5 KB

    const int tid = threadIdx.x;
    const int tx = tid & 15;             // col group (4 cols)
    const int ty = tid >> 4;             // row group (8 rows)
    const int row0 = blockIdx.x << 7;

    const float* __restrict__ Xp = FROM_GO ? g_O : X;

    float acc[8][4];
#pragma unroll
    for (int r = 0; r < 8; r++)
#pragma unroll
        for (int c = 0; c < 4; c++) acc[r][c] = 0.f;

    for (int kk = 0; kk < K; kk += KC) {
#pragma unroll
        for (int p = 0; p < 2; p++) {
            int j = tid + (p << 8);
            int r = j >> 4;
            int cp = (j & 15) << 2;
            *(float4*)&Ws[r * 64 + cp] = *(const float4*)&W[(size_t)(kk + r) * HID + cp];
        }
#pragma unroll
        for (int p = 0; p < 4; p++) {
            int j = tid + (p << 8);
            int r = j >> 3;
            int cp = (j & 7) << 2;
            int grow = row0 + r;
            float4 v = make_float4(0.f, 0.f, 0.f, 0.f);
            if (grow < M) {
                v = *(const float4*)&Xp[(size_t)grow * K + kk + cp];
                if (RELU) {
                    v.x = fmaxf(v.x, 0.f); v.y = fmaxf(v.y, 0.f);
                    v.z = fmaxf(v.z, 0.f); v.w = fmaxf(v.w, 0.f);
                }
            }
            float* xs = &Xs[r * 33 + cp];
            xs[0] = v.x; xs[1] = v.y; xs[2] = v.z; xs[3] = v.w;
        }
        __syncthreads();

#pragma unroll
        for (int k = 0; k < KC; k++) {
            float4 b4 = *(float4*)&Ws[k * 64 + (tx << 2)];
            float a[8];
#pragma unroll
            for (int r = 0; r < 8; r++) a[r] = Xs[(ty * 8 + r) * 33 + k];
#pragma unroll
            for (int r = 0; r < 8; r++) {
                acc[r][0] += a[r] * b4.x;
                acc[r][1] += a[r] * b4.y;
                acc[r][2] += a[r] * b4.z;
                acc[r][3] += a[r] * b4.w;
            }
        }
        __syncthreads();
    }

    // store fp16 H tile (8B per row-slice per thread)
#pragma unroll
    for (int r = 0; r < 8; r++) {
        int grow = row0 + ty * 8 + r;
        if (grow < M) {
            __half2 h0 = __floats2half2_rn(acc[r][0], acc[r][1]);
            __half2 h1 = __floats2half2_rn(acc[r][2], acc[r][3]);
            __half2 pack[2] = {h0, h1};
            *(float2*)&g_Hh[(size_t)grow * HID + (tx << 2)] = *(float2*)pack;
        }
    }

    // fused attention-logit epilogue (reduce across the 16 tx lanes)
    float4 as4 = *(const float4*)&as[tx << 2];
    float4 ad4 = *(const float4*)&ad[tx << 2];
    float pes[8], ped[8];
#pragma unroll
    for (int r = 0; r < 8; r++) {
        pes[r] = acc[r][0] * as4.x + acc[r][1] * as4.y + acc[r][2] * as4.z + acc[r][3] * as4.w;
        ped[r] = acc[r][0] * ad4.x + acc[r][1] * ad4.y + acc[r][2] * ad4.z + acc[r][3] * ad4.w;
    }
#pragma unroll
    for (int o = 8; o; o >>= 1) {
#pragma unroll
        for (int r = 0; r < 8; r++) {
            pes[r] += __shfl_xor_sync(0xffffffffu, pes[r], o);
            ped[r] += __shfl_xor_sync(0xffffffffu, ped[r], o);
        }
    }
    if (tx == 0) {
#pragma unroll
        for (int r = 0; r < 8; r++) {
            int grow = row0 + ty * 8 + r;
            if (grow < M) {
                float es = pes[r], ed = ped[r];
                g_es[grow] = es;
                g_ed[grow] = ed;
                g_selfe[grow] = leaky(es + ed);
            }
        }
    }
}

// ---------------------------------------------------------------------------
// Fused softmax + aggregate: one warp per dst node, zero atomics.
// Pass C gathers fp16 features (128B/edge instead of 256B).
// ---------------------------------------------------------------------------
template<bool FINAL>
__global__ void __launch_bounds__(256)
agg_k(const float* __restrict__ b, float* __restrict__ out, int N) {
    int node = (blockIdx.x * 256 + threadIdx.x) >> 5;
    int lane = threadIdx.x & 31;
    if (node >= N) return;

    int beg = g_off[node], end = g_off[node + 1];
    float edn = g_ed[node];
    float selfe = g_selfe[node];

    // pass A: logits + max
    float m = selfe;
    for (int i = beg + lane; i < end; i += 32) {
        int s = g_csrc[i];
        float e = leaky(g_es[s] + edn);
        g_ew[i] = e;
        m = fmaxf(m, e);
    }
#pragma unroll
    for (int o = 16; o; o >>= 1) m = fmaxf(m, __shfl_xor_sync(0xffffffffu, m, o));

    // pass B: exp + sum
    float wself = __expf(selfe - m);
    float ssum = (lane == 0) ? wself : 0.f;
    for (int i = beg + lane; i < end; i += 32) {
        float ex = __expf(g_ew[i] - m);
        g_ew[i] = ex;
        ssum += ex;
    }
#pragma unroll
    for (int o = 16; o; o >>= 1) ssum += __shfl_xor_sync(0xffffffffu, ssum, o);

    // pass C: weighted fp16 feature gather, 2 edges/iter (16 lanes x 4 halves)
    int half_ = lane >> 4;
    int q = (lane & 15) << 2;
    float4 acc = make_float4(0.f, 0.f, 0.f, 0.f);
    if (half_ == 0) {
        float2 raw = *(const float2*)&g_Hh[(size_t)node * HID + q];
        __half2 h0 = *(__half2*)&raw.x;
        __half2 h1 = *(__half2*)&raw.y;
        float2 lo = __half22float2(h0), hi = __half22float2(h1);
        acc.x = wself * lo.x; acc.y = wself * lo.y;
        acc.z = wself * hi.x; acc.w = wself * hi.y;
    }
    for (int i = beg + half_; i < end; i += 2) {
        int s = g_csrc[i];
        float wt = g_ew[i];
        float2 raw = *(const float2*)&g_Hh[(size_t)s * HID + q];
        __half2 h0 = *(__half2*)&raw.x;
        __half2 h1 = *(__half2*)&raw.y;
        float2 lo = __half22float2(h0), hi = __half22float2(h1);
        acc.x += wt * lo.x; acc.y += wt * lo.y;
        acc.z += wt * hi.x; acc.w += wt * hi.y;
    }
    acc.x += __shfl_xor_sync(0xffffffffu, acc.x, 16);
    acc.y += __shfl_xor_sync(0xffffffffu, acc.y, 16);
    acc.z += __shfl_xor_sync(0xffffffffu, acc.z, 16);
    acc.w += __shfl_xor_sync(0xffffffffu, acc.w, 16);

    if (half_ == 0) {
        float inv = 1.f / ssum;
        float4 b4 = *(const float4*)&b[q];
        float* dst = FINAL ? out : g_O;
        *(float4*)&dst[(size_t)node * HID + q] =
            make_float4(acc.x * inv + b4.x, acc.y * inv + b4.y,
                        acc.z * inv + b4.z, acc.w * inv + b4.w);
    }
}

// ---------------------------------------------------------------------------
// host driver
// ---------------------------------------------------------------------------
extern "C" void kernel_launch(void* const* d_in, const int* in_sizes, int n_in,
                              void* d_out, int out_size) {
    const float* x   = (const float*)d_in[0];
    const void*  ei  = d_in[1];
    const float* W1  = (const float*)d_in[2];
    const float* as1 = (const float*)d_in[3];
    const float* ad1 = (const float*)d_in[4];
    const float* b1  = (const float*)d_in[5];
    const float* W2  = (const float*)d_in[6];
    const float* as2 = (const float*)d_in[7];
    const float* ad2 = (const float*)d_in[8];
    const float* b2  = (const float*)d_in[9];
    const float* W3  = (const float*)d_in[10];
    const float* as3 = (const float*)d_in[11];
    const float* ad3 = (const float*)d_in[12];
    const float* b3  = (const float*)d_in[13];

    int hid = in_sizes[3];            // 64
    int fin = in_sizes[2] / hid;      // 128
    int N   = in_sizes[0] / fin;
    int E   = in_sizes[1] / 2;
    float* out = (float*)d_out;

    // edge index dtype detect
    int nscan = 4096;
    if (nscan > E / 2) nscan = E / 2 > 0 ? E / 2 : 1;
    detect_dtype<<<1, 256>>>((const unsigned long long*)ei, nscan);

    // CSR build (once, reused by 3 layers) — reads edge_index directly
    int nb = (N + SCAN_B - 1) / SCAN_B;
    zero_cnt<<<(N + 255) / 256, 256>>>(N);
    hist_k<<<(E + 255) / 256, 256>>>(ei, E, N);
    scan_block<<<nb, SCAN_B>>>(N);
    scan_bsums<<<1, SCAN_B>>>(nb);
    add_offsets<<<(N + 255) / 256, 256>>>(N);
    copy_cursor<<<(N + 255) / 256, 256>>>(N);
    fill_csr<<<(E + 255) / 256, 256>>>(ei, E, N);

    int gblk = (N + 127) / 128;
    int ablk = (N * 32 + 255) / 256;

    // layer 1
    gemm_k<false, false><<<gblk, 256>>>(x, W1, as1, ad1, N, fin);
    agg_k<false><<<ablk, 256>>>(b1, nullptr, N);
    // layer 2
    gemm_k<true, true><<<gblk, 256>>>(nullptr, W2, as2, ad2, N, hid);
    agg_k<false><<<ablk, 256>>>(b2, nullptr, N);
    // layer 3
    gemm_k<true, true><<<gblk, 256>>>(nullptr, W3, as3, ad3, N, hid);
    agg_k<true><<<ablk, 256>>>(b3, out, N);
}

// round 13
// speedup vs baseline: 1.2891x; 1.1089x over previous
#include <cuda_runtime.h>
#include <cuda_fp16.h>
#include <cstdint>

// ---------------------------------------------------------------------------
// GAT (3 layers, single head) on GB300 — CSR + fp16-gather + HMMA GEMM.
//  0: x [N, F_IN] f32
//  1: edge_index [2, E] (runtime-detected int32 vs int64)
//  2..5:  W1 [F_IN,64], a_src1[64], a_dst1[64], b1[64]
//  6..9:  W2, as2, ad2, b2     10..13: W3, as3, ad3, b3
// output: [N, 64] f32
// ---------------------------------------------------------------------------

#define HID 64
#define NMAX 131072
#define EMAX 3400000
#define SCAN_B 512

__device__ __align__(16) int      g_csrc[EMAX];     // CSR: src ids grouped by dst
__device__ __align__(16) float    g_ew[EMAX];       // per-CSR-slot e, then exp(e-m)
__device__ __align__(16) int      g_cnt[NMAX];      // histogram, then fill cursor
__device__ __align__(16) int      g_off[NMAX + 1];  // CSR row offsets
__device__ __align__(16) int      g_bsum[1024];
__device__ __align__(16) __half   g_Hh[(size_t)NMAX * HID];  // hidden, fp16 (gather)
__device__ __align__(16) float    g_O[(size_t)NMAX * HID];   // aggregated output
__device__ __align__(16) float    g_es[NMAX];
__device__ __align__(16) float    g_ed[NMAX];
__device__ __align__(16) float    g_selfe[NMAX];
__device__ int g_is32;

__device__ __forceinline__ float leaky(float v) { return v > 0.f ? v : 0.2f * v; }

// ---------------------------------------------------------------------------
// dtype detection: int32 buffer read as u64 packs two ids -> values >= 2^32
// ---------------------------------------------------------------------------
__global__ void detect_dtype(const unsigned long long* __restrict__ ei, int nscan) {
    __shared__ int flag;
    if (threadIdx.x == 0) flag = 0;
    __syncthreads();
    for (int j = threadIdx.x; j < nscan; j += blockDim.x)
        if (ei[j] >= 0x100000000ull) flag = 1;
    __syncthreads();
    if (threadIdx.x == 0) g_is32 = flag;
}

__device__ __forceinline__ int load_id(const void* eiv, size_t idx) {
    if (g_is32) return ((const int*)eiv)[idx];
    return (int)((const long long*)eiv)[idx];
}

// ---------------------------------------------------------------------------
// CSR build (edge_index read directly; no staging arrays)
// ---------------------------------------------------------------------------
__global__ void zero_cnt(int N) {
    int i = blockIdx.x * blockDim.x + threadIdx.x;
    if (i < N) g_cnt[i] = 0;
}
__global__ void hist_k(const void* __restrict__ eiv, int E, int N) {
    int i = blockIdx.x * blockDim.x + threadIdx.x;
    if (i >= E) return;
    int d = load_id(eiv, (size_t)E + i);
    d = min(max(d, 0), N - 1);
    atomicAdd(&g_cnt[d], 1);
}
__global__ void __launch_bounds__(SCAN_B) scan_block(int N) {
    __shared__ int ws[SCAN_B / 32];
    int tid = threadIdx.x;
    int gi = blockIdx.x * SCAN_B + tid;
    int v = (gi < N) ? g_cnt[gi] : 0;
    int lane = tid & 31, wid = tid >> 5;
    int x = v;
#pragma unroll
    for (int o = 1; o < 32; o <<= 1) {
        int y = __shfl_up_sync(0xffffffffu, x, o);
        if (lane >= o) x += y;
    }
    if (lane == 31) ws[wid] = x;
    __syncthreads();
    if (wid == 0) {
        int t = (lane < SCAN_B / 32) ? ws[lane] : 0;
#pragma unroll
        for (int o = 1; o < SCAN_B / 32; o <<= 1) {
            int y = __shfl_up_sync(0xffffffffu, t, o);
            if (lane >= o) t += y;
        }
        if (lane < SCAN_B / 32) ws[lane] = t;
    }
    __syncthreads();
    int incl = x + (wid > 0 ? ws[wid - 1] : 0);
    if (gi < N) g_off[gi + 1] = incl;
    if (tid == SCAN_B - 1) g_bsum[blockIdx.x] = incl;
}
__global__ void __launch_bounds__(SCAN_B) scan_bsums(int nb) {
    __shared__ int ws[SCAN_B / 32];
    int tid = threadIdx.x;
    int v = (tid < nb) ? g_bsum[tid] : 0;
    int lane = tid & 31, wid = tid >> 5;
    int x = v;
#pragma unroll
    for (int o = 1; o < 32; o <<= 1) {
        int y = __shfl_up_sync(0xffffffffu, x, o);
        if (lane >= o) x += y;
    }
    if (lane == 31) ws[wid] = x;
    __syncthreads();
    if (wid == 0) {
        int t = (lane < SCAN_B / 32) ? ws[lane] : 0;
#pragma unroll
        for (int o = 1; o < SCAN_B / 32; o <<= 1) {
            int y = __shfl_up_sync(0xffffffffu, t, o);
            if (lane >= o) t += y;
        }
        if (lane < SCAN_B / 32) ws[lane] = t;
    }
    __syncthreads();
    int incl = x + (wid > 0 ? ws[wid - 1] : 0);
    if (tid < nb) g_bsum[tid] = incl - v;   // exclusive
}
__global__ void add_offsets(int N) {
    int gi = blockIdx.x * blockDim.x + threadIdx.x;
    if (gi == 0) g_off[0] = 0;
    if (gi < N) g_off[gi + 1] += g_bsum[gi / SCAN_B];
}
__global__ void copy_cursor(int N) {
    int i = blockIdx.x * blockDim.x + threadIdx.x;
    if (i < N) g_cnt[i] = g_off[i];
}
__global__ void fill_csr(const void* __restrict__ eiv, int E, int N) {
    int i = blockIdx.x * blockDim.x + threadIdx.x;
    if (i >= E) return;
    int s = load_id(eiv, i);
    int d = load_id(eiv, (size_t)E + i);
    s = min(max(s, 0), N - 1);
    d = min(max(d, 0), N - 1);
    int pos = atomicAdd(&g_cnt[d], 1);
    g_csrc[pos] = s;
}

// ---------------------------------------------------------------------------
// HMMA GEMM: act(X[M,K]) @ W[K,64] -> g_Hh (fp16) via mma.sync m16n8k16.
// 128x64 block tile, 8 warps; warp w owns rows [w*16, w*16+16).
// fp16 operands in smem (stride 40 halves: conflict-free fragment loads),
// fp32 accumulators. Fused epilogue: es/ed/selfe from fragments.
// ---------------------------------------------------------------------------
#define KC 32
#define XS_STR 40   // halves; (row*20 + t) spans all 32 banks for g=0..7
template<bool RELU, bool FROM_GO>
__global__ void __launch_bounds__(256)
gemm_k(const float* __restrict__ X, const float* __restrict__ W,
       const float* __restrict__ as, const float* __restrict__ ad,
       int M, int K) {
    __shared__ __half Xs[128 * XS_STR];   // 10 KB
    __shared__ __half Wt[64 * XS_STR];    // 5 KB, transposed W chunk [n][k]

    const int tid = threadIdx.x;
    const int lane = tid & 31;
    const int warp = tid >> 5;
    const int g = lane >> 2;          // fragment group row / B n-index
    const int t = lane & 3;           // thread-in-group (k pairs / D col pairs)
    const int wr0 = warp << 4;        // warp's first row in tile
    const int row0 = blockIdx.x << 7;

    const float* __restrict__ Xp = FROM_GO ? g_O : X;

    float acc[8][4];
#pragma unroll
    for (int n = 0; n < 8; n++)
#pragma unroll
        for (int c = 0; c < 4; c++) acc[n][c] = 0.f;

    for (int kk = 0; kk < K; kk += KC) {
        // --- load X chunk [128, KC] fp32 -> fp16 smem (each thread: 1 row-half) ---
        {
            int r = tid >> 1;                  // 0..127
            int c0 = (tid & 1) << 4;           // 0 or 16
            int grow = row0 + r;
            __half2* xs = (__half2*)&Xs[r * XS_STR + c0];
#pragma unroll
            for (int p = 0; p < 4; p++) {
                float4 v = make_float4(0.f, 0.f, 0.f, 0.f);
                if (grow < M)
                    v = *(const float4*)&Xp[(size_t)grow * K + kk + c0 + (p << 2)];
                if (RELU) {
                    v.x = fmaxf(v.x, 0.f); v.y = fmaxf(v.y, 0.f);
                    v.z = fmaxf(v.z, 0.f); v.w = fmaxf(v.w, 0.f);
                }
                xs[p * 2 + 0] = __floats2half2_rn(v.x, v.y);
                xs[p * 2 + 1] = __floats2half2_rn(v.z, v.w);
            }
        }
        // --- load + transpose W chunk [KC,64] -> Wt[n][k] fp16 ---
        {
#pragma unroll
            for (int i = 0; i < 4; i++) {
                int k = warp + (i << 3);       // 0..31
                float w0 = W[(size_t)(kk + k) * HID + lane];
                float w1 = W[(size_t)(kk + k) * HID + lane + 32];
                Wt[lane * XS_STR + k]        = __float2half_rn(w0);
                Wt[(lane + 32) * XS_STR + k] = __float2half_rn(w1);
            }
        }
        __syncthreads();

        // --- two k16 MMA steps ---
#pragma unroll
        for (int ks = 0; ks < 2; ks++) {
            int k0 = ks << 4;
            uint32_t a0 = *(uint32_t*)&Xs[(wr0 + g) * XS_STR + k0 + 2 * t];
            uint32_t a1 = *(uint32_t*)&Xs[(wr0 + g + 8) * XS_STR + k0 + 2 * t];
            uint32_t a2 = *(uint32_t*)&Xs[(wr0 + g) * XS_STR + k0 + 2 * t + 8];
            uint32_t a3 = *(uint32_t*)&Xs[(wr0 + g + 8) * XS_STR + k0 + 2 * t + 8];
#pragma unroll
            for (int n = 0; n < 8; n++) {
                uint32_t b0 = *(uint32_t*)&Wt[(n * 8 + g) * XS_STR + k0 + 2 * t];
                uint32_t b1 = *(uint32_t*)&Wt[(n * 8 + g) * XS_STR + k0 + 2 * t + 8];
                asm volatile(
                    "mma.sync.aligned.m16n8k16.row.col.f32.f16.f16.f32 "
                    "{%0,%1,%2,%3}, {%4,%5,%6,%7}, {%8,%9}, {%0,%1,%2,%3};"
                    : "+f"(acc[n][0]), "+f"(acc[n][1]), "+f"(acc[n][2]), "+f"(acc[n][3])
                    : "r"(a0), "r"(a1), "r"(a2), "r"(a3), "r"(b0), "r"(b1));
            }
        }
        __syncthreads();
    }

    // --- store fp16 H (rows wr0+g, wr0+g+8; cols 8n+2t..+1) ---
    int rowA = row0 + wr0 + g;
    int rowB = rowA + 8;
#pragma unroll
    for (int n = 0; n < 8; n++) {
        int col = n * 8 + 2 * t;
        if (rowA < M)
            *(__half2*)&g_Hh[(size_t)rowA * HID + col] = __floats2half2_rn(acc[n][0], acc[n][1]);
        if (rowB < M)
            *(__half2*)&g_Hh[(size_t)rowB * HID + col] = __floats2half2_rn(acc[n][2], acc[n][3]);
    }

    // --- fused attention-logit epilogue ---
    float esA = 0.f, edA = 0.f, esB = 0.f, edB = 0.f;
#pragma unroll
    for (int n = 0; n < 8; n++) {
        int col = n * 8 + 2 * t;
        float s0 = __ldg(&as[col]), s1 = __ldg(&as[col + 1]);
        float d0 = __ldg(&ad[col]), d1 = __ldg(&ad[col + 1]);
        esA += acc[n][0] * s0 + acc[n][1] * s1;
        edA += acc[n][0] * d0 + acc[n][1] * d1;
        esB += acc[n][2] * s0 + acc[n][3] * s1;
        edB += acc[n][2] * d0 + acc[n][3] * d1;
    }
#pragma unroll
    for (int o = 1; o < 4; o <<= 1) {
        esA += __shfl_xor_sync(0xffffffffu, esA, o);
        edA += __shfl_xor_sync(0xffffffffu, edA, o);
        esB += __shfl_xor_sync(0xffffffffu, esB, o);
        edB += __shfl_xor_sync(0xffffffffu, edB, o);
    }
    if (t == 0) {
        if (rowA < M) {
            g_es[rowA] = esA; g_ed[rowA] = edA; g_selfe[rowA] = leaky(esA + edA);
        }
        if (rowB < M) {
            g_es[rowB] = esB; g_ed[rowB] = edB; g_selfe[rowB] = leaky(esB + edB);
        }
    }
}

// ---------------------------------------------------------------------------
// Fused softmax + aggregate: one warp per dst node, zero atomics.
// Pass C gathers fp16 features (128B/edge).
// ---------------------------------------------------------------------------
template<bool FINAL>
__global__ void __launch_bounds__(256)
agg_k(const float* __restrict__ b, float* __restrict__ out, int N) {
    int node = (blockIdx.x * 256 + threadIdx.x) >> 5;
    int lane = threadIdx.x & 31;
    if (node >= N) return;

    int beg = g_off[node], end = g_off[node + 1];
    float edn = g_ed[node];
    float selfe = g_selfe[node];

    // pass A: logits + max
    float m = selfe;
    for (int i = beg + lane; i < end; i += 32) {
        int s = g_csrc[i];
        float e = leaky(g_es[s] + edn);
        g_ew[i] = e;
        m = fmaxf(m, e);
    }
#pragma unroll
    for (int o = 16; o; o >>= 1) m = fmaxf(m, __shfl_xor_sync(0xffffffffu, m, o));

    // pass B: exp + sum
    float wself = __expf(selfe - m);
    float ssum = (lane == 0) ? wself : 0.f;
    for (int i = beg + lane; i < end; i += 32) {
        float ex = __expf(g_ew[i] - m);
        g_ew[i] = ex;
        ssum += ex;
    }
#pragma unroll
    for (int o = 16; o; o >>= 1) ssum += __shfl_xor_sync(0xffffffffu, ssum, o);

    // pass C: weighted fp16 feature gather, 2 edges/iter
    int half_ = lane >> 4;
    int q = (lane & 15) << 2;
    float4 acc = make_float4(0.f, 0.f, 0.f, 0.f);
    if (half_ == 0) {
        float2 raw = *(const float2*)&g_Hh[(size_t)node * HID + q];
        __half2 h0 = *(__half2*)&raw.x;
        __half2 h1 = *(__half2*)&raw.y;
        float2 lo = __half22float2(h0), hi = __half22float2(h1);
        acc.x = wself * lo.x; acc.y = wself * lo.y;
        acc.z = wself * hi.x; acc.w = wself * hi.y;
    }
    for (int i = beg + half_; i < end; i += 2) {
        int s = g_csrc[i];
        float wt = g_ew[i];
        float2 raw = *(const float2*)&g_Hh[(size_t)s * HID + q];
        __half2 h0 = *(__half2*)&raw.x;
        __half2 h1 = *(__half2*)&raw.y;
        float2 lo = __half22float2(h0), hi = __half22float2(h1);
        acc.x += wt * lo.x; acc.y += wt * lo.y;
        acc.z += wt * hi.x; acc.w += wt * hi.y;
    }
    acc.x += __shfl_xor_sync(0xffffffffu, acc.x, 16);
    acc.y += __shfl_xor_sync(0xffffffffu, acc.y, 16);
    acc.z += __shfl_xor_sync(0xffffffffu, acc.z, 16);
    acc.w += __shfl_xor_sync(0xffffffffu, acc.w, 16);

    if (half_ == 0) {
        float inv = 1.f / ssum;
        float4 b4 = *(const float4*)&b[q];
        float* dst = FINAL ? out : g_O;
        *(float4*)&dst[(size_t)node * HID + q] =
            make_float4(acc.x * inv + b4.x, acc.y * inv + b4.y,
                        acc.z * inv + b4.z, acc.w * inv + b4.w);
    }
}

// ---------------------------------------------------------------------------
// host driver
// ---------------------------------------------------------------------------
extern "C" void kernel_launch(void* const* d_in, const int* in_sizes, int n_in,
                              void* d_out, int out_size) {
    const float* x   = (const float*)d_in[0];
    const void*  ei  = d_in[1];
    const float* W1  = (const float*)d_in[2];
    const float* as1 = (const float*)d_in[3];
    const float* ad1 = (const float*)d_in[4];
    const float* b1  = (const float*)d_in[5];
    const float* W2  = (const float*)d_in[6];
    const float* as2 = (const float*)d_in[7];
    const float* ad2 = (const float*)d_in[8];
    const float* b2  = (const float*)d_in[9];
    const float* W3  = (const float*)d_in[10];
    const float* as3 = (const float*)d_in[11];
    const float* ad3 = (const float*)d_in[12];
    const float* b3  = (const float*)d_in[13];

    int hid = in_sizes[3];            // 64
    int fin = in_sizes[2] / hid;      // 128
    int N   = in_sizes[0] / fin;
    int E   = in_sizes[1] / 2;
    float* out = (float*)d_out;

    // edge index dtype detect
    int nscan = 4096;
    if (nscan > E / 2) nscan = E / 2 > 0 ? E / 2 : 1;
    detect_dtype<<<1, 256>>>((const unsigned long long*)ei, nscan);

    // CSR build (once, reused by 3 layers)
    int nb = (N + SCAN_B - 1) / SCAN_B;
    zero_cnt<<<(N + 255) / 256, 256>>>(N);
    hist_k<<<(E + 255) / 256, 256>>>(ei, E, N);
    scan_block<<<nb, SCAN_B>>>(N);
    scan_bsums<<<1, SCAN_B>>>(nb);
    add_offsets<<<(N + 255) / 256, 256>>>(N);
    copy_cursor<<<(N + 255) / 256, 256>>>(N);
    fill_csr<<<(E + 255) / 256, 256>>>(ei, E, N);

    int gblk = (N + 127) / 128;
    int ablk = (N * 32 + 255) / 256;

    // layer 1
    gemm_k<false, false><<<gblk, 256>>>(x, W1, as1, ad1, N, fin);
    agg_k<false><<<ablk, 256>>>(b1, nullptr, N);
    // layer 2
    gemm_k<true, true><<<gblk, 256>>>(nullptr, W2, as2, ad2, N, hid);
    agg_k<false><<<ablk, 256>>>(b2, nullptr, N);
    // layer 3
    gemm_k<true, true><<<gblk, 256>>>(nullptr, W3, as3, ad3, N, hid);
    agg_k<true><<<ablk, 256>>>(b3, out, N);
}